// round 15
// baseline (speedup 1.0000x reference)
#include <cuda_runtime.h>
#include <cstdint>

// GMP forward:
// out[b,j] = sum_{i=0..7} xc[b, j+i-7] * F_i(j+i-7)
// F_i(n)   = W[i,0] + sum_{m=0..7} a(n+m-7)*(w1 + a*(w2 + a*w3))   (Horner)
// with (w1,w2,w3) = W[i, 1+3m+{0,1,2}]; xc,a zero-extended for n<0.
// Two consecutive outputs per f32x2 (FFMA2); weights pre-duplicated in shared.

constexpr int Bn  = 64;
constexpr int Tn  = 16384;
constexpr int Mm  = 8;
constexpr int CH  = 4;       // samples per thread
constexpr int TPB = 128;
constexpr int WIN = CH + 14; // 18

using u64 = unsigned long long;

__device__ __forceinline__ u64 pk2(float lo, float hi) {
    u64 r;
    unsigned lo_u = __float_as_uint(lo), hi_u = __float_as_uint(hi);
    asm("mov.b64 %0, {%1, %2};" : "=l"(r) : "r"(lo_u), "r"(hi_u));
    return r;
}
__device__ __forceinline__ void upk2(u64 v, float& lo, float& hi) {
    unsigned lo_u, hi_u;
    asm("mov.b64 {%0, %1}, %2;" : "=r"(lo_u), "=r"(hi_u) : "l"(v));
    lo = __uint_as_float(lo_u); hi = __uint_as_float(hi_u);
}
__device__ __forceinline__ u64 fma2(u64 a, u64 b, u64 c) {
    u64 r;
    asm("fma.rn.f32x2 %0, %1, %2, %3;" : "=l"(r) : "l"(a), "l"(b), "l"(c));
    return r;
}
__device__ __forceinline__ float sqrt_approx(float x) {
    float r;
    asm("sqrt.approx.f32 %0, %1;" : "=f"(r) : "f"(x));
    return r;
}

__global__ __launch_bounds__(TPB)
void gmp_kernel(const float2* __restrict__ x,     // (B,T) complex as float2
                const float*  __restrict__ W,     // (8,25)
                float2*       __restrict__ out)   // (B,T) complex as float2
{
    // Duplicated weight pairs: sWd[(i*8+m)*4 + {0,1,2}] = (w1,w1),(w2,w2),(w3,w3)
    // (stride 4 u64 = 32B keeps 16B alignment for the ulonglong2 load).
    __shared__ u64 sWd[Mm * Mm * 4];
    __shared__ u64 sW0d[Mm];
    for (int q = threadIdx.x; q < Mm * Mm; q += TPB) {
        const int i = q >> 3, m = q & 7;
        const float* wr = W + i * 25 + 1 + 3 * m;
        sWd[q * 4 + 0] = pk2(wr[0], wr[0]);
        sWd[q * 4 + 1] = pk2(wr[1], wr[1]);
        sWd[q * 4 + 2] = pk2(wr[2], wr[2]);
    }
    if (threadIdx.x < Mm) {
        const float w0 = W[threadIdx.x * 25];
        sW0d[threadIdx.x] = pk2(w0, w0);
    }
    __syncthreads();

    const int per_row = Tn / CH;                       // 4096
    const int idx = blockIdx.x * TPB + threadIdx.x;    // < B*per_row
    const int b   = idx / per_row;
    const int j0  = (idx - b * per_row) * CH;

    const float2* xrow = x + (size_t)b * Tn;

    // Complex window: k in [0,18), n = j0 + k - 14. j0 multiple of 4 ->
    // pair starts even & 16B-aligned; a pair is fully valid or fully zero.
    float xr[WIN], xi[WIN];
#pragma unroll
    for (int kp = 0; kp < WIN / 2; kp++) {
        const int k = 2 * kp;
        const int n = j0 + k - 14;
        float4 v;
        if (n >= 0) v = *reinterpret_cast<const float4*>(xrow + n);
        else        v = make_float4(0.f, 0.f, 0.f, 0.f);
        xr[k]     = v.x; xi[k]     = v.y;
        xr[k + 1] = v.z; xi[k + 1] = v.w;
    }

    // Envelope a = |xc| (approx sqrt: ~2^-21 rel err, 0 -> 0), packed at both
    // parities: ae[h]=(a[2h],a[2h+1]) h=0..8; ao[h]=(a[2h+1],a[2h+2]) h=0..7.
    float a[WIN];
#pragma unroll
    for (int k = 0; k < WIN; k++)
        a[k] = sqrt_approx(fmaf(xr[k], xr[k], xi[k] * xi[k]));

    u64 ae[9], ao[8];
#pragma unroll
    for (int h = 0; h < 9; h++) ae[h] = pk2(a[2 * h], a[2 * h + 1]);
#pragma unroll
    for (int h = 0; h < 8; h++) ao[h] = pk2(a[2 * h + 1], a[2 * h + 2]);

    float or_[CH], oi_[CH];
#pragma unroll
    for (int c = 0; c < CH; c++) { or_[c] = 0.f; oi_[c] = 0.f; }

#pragma unroll
    for (int i = 0; i < Mm; i++) {
        const u64 w0p = sW0d[i];
        u64 F[CH / 2];

#pragma unroll
        for (int m = 0; m < Mm; m++) {
            const ulonglong2 w12 = *reinterpret_cast<const ulonglong2*>(&sWd[(i * Mm + m) * 4]);
            const u64 w3d = sWd[(i * Mm + m) * 4 + 2];
            const int s    = i + m;        // compile-time constant
            const int base = s >> 1;
#pragma unroll
            for (int cp = 0; cp < CH / 2; cp++) {
                // pair covers t_lo = 2*cp + s, t_hi = t_lo + 1 (t = c+i+m)
                const u64 av = (s & 1) ? ao[base + cp] : ae[base + cp];
                const u64 t1 = fma2(av, w3d, w12.y);
                const u64 t2 = fma2(av, t1,  w12.x);
                F[cp] = fma2(av, t2, (m == 0) ? w0p : F[cp]);
            }
        }

        // Tail: complex tap accumulation (scalar; xk parity varies with i).
#pragma unroll
        for (int cp = 0; cp < CH / 2; cp++) {
            float Flo, Fhi; upk2(F[cp], Flo, Fhi);
            const int c  = 2 * cp;
            const int xk = c + i + 7;      // x-index for n = j0+c+i-7
            or_[c]     = fmaf(xr[xk],     Flo, or_[c]);
            oi_[c]     = fmaf(xi[xk],     Flo, oi_[c]);
            or_[c + 1] = fmaf(xr[xk + 1], Fhi, or_[c + 1]);
            oi_[c + 1] = fmaf(xi[xk + 1], Fhi, oi_[c + 1]);
        }
    }

    // Vectorized store: 2x STG.128.
    float4* orow4 = reinterpret_cast<float4*>(out + (size_t)b * Tn + j0);
#pragma unroll
    for (int c4 = 0; c4 < CH / 2; c4++)
        orow4[c4] = make_float4(or_[2 * c4], oi_[2 * c4],
                                or_[2 * c4 + 1], oi_[2 * c4 + 1]);
}

extern "C" void kernel_launch(void* const* d_in, const int* in_sizes, int n_in,
                              void* d_out, int out_size)
{
    const float2* x = (const float2*)d_in[0];
    // d_in[1] = h_0 (unused)
    const float*  W = (const float*)d_in[2];
    float2* out = (float2*)d_out;

    const int total_threads = Bn * (Tn / CH);      // 262144
    const int grid = total_threads / TPB;          // 2048
    gmp_kernel<<<grid, TPB>>>(x, W, out);
}

// round 16
// speedup vs baseline: 1.0150x; 1.0150x over previous
#include <cuda_runtime.h>
#include <cstdint>

// GMP forward:
// out[b,j] = sum_{i=0..7} xc[b, j+i-7] * F_i(j+i-7)
// F_i(n)   = W[i,0] + sum_{m=0..7} a(n+m-7)*(w1 + a*(w2 + a*w3))   (Horner)
// with (w1,w2,w3) = W[i, 1+3m+{0,1,2}]; xc,a zero-extended for n<0.
// Two consecutive outputs per f32x2 (FFMA2); weights pre-duplicated in shared.

constexpr int Bn  = 64;
constexpr int Tn  = 16384;
constexpr int Mm  = 8;
constexpr int CH  = 4;       // samples per thread
constexpr int TPB = 128;
constexpr int WIN = CH + 14; // 18

using u64 = unsigned long long;

__device__ __forceinline__ u64 pk2(float lo, float hi) {
    u64 r;
    unsigned lo_u = __float_as_uint(lo), hi_u = __float_as_uint(hi);
    asm("mov.b64 %0, {%1, %2};" : "=l"(r) : "r"(lo_u), "r"(hi_u));
    return r;
}
__device__ __forceinline__ void upk2(u64 v, float& lo, float& hi) {
    unsigned lo_u, hi_u;
    asm("mov.b64 {%0, %1}, %2;" : "=r"(lo_u), "=r"(hi_u) : "l"(v));
    lo = __uint_as_float(lo_u); hi = __uint_as_float(hi_u);
}
__device__ __forceinline__ u64 fma2(u64 a, u64 b, u64 c) {
    u64 r;
    asm("fma.rn.f32x2 %0, %1, %2, %3;" : "=l"(r) : "l"(a), "l"(b), "l"(c));
    return r;
}
__device__ __forceinline__ float sqrt_approx(float x) {
    float r;
    asm("sqrt.approx.f32 %0, %1;" : "=f"(r) : "f"(x));
    return r;
}

__global__ __launch_bounds__(TPB)
void gmp_kernel(const float2* __restrict__ x,     // (B,T) complex as float2
                const float*  __restrict__ W,     // (8,25)
                float2*       __restrict__ out)   // (B,T) complex as float2
{
    // Duplicated weight pairs: sWd[(i*8+m)*4 + {0,1,2}] = (w1,w1),(w2,w2),(w3,w3)
    // (stride 4 u64 = 32B keeps 16B alignment for the ulonglong2 load).
    __shared__ u64 sWd[Mm * Mm * 4];
    __shared__ u64 sW0d[Mm];
    for (int q = threadIdx.x; q < Mm * Mm; q += TPB) {
        const int i = q >> 3, m = q & 7;
        const float* wr = W + i * 25 + 1 + 3 * m;
        sWd[q * 4 + 0] = pk2(wr[0], wr[0]);
        sWd[q * 4 + 1] = pk2(wr[1], wr[1]);
        sWd[q * 4 + 2] = pk2(wr[2], wr[2]);
    }
    if (threadIdx.x < Mm) {
        const float w0 = W[threadIdx.x * 25];
        sW0d[threadIdx.x] = pk2(w0, w0);
    }
    __syncthreads();

    const int per_row = Tn / CH;                       // 4096
    const int idx = blockIdx.x * TPB + threadIdx.x;    // < B*per_row
    const int b   = idx / per_row;
    const int j0  = (idx - b * per_row) * CH;

    const float2* xrow = x + (size_t)b * Tn;

    // Complex window: k in [0,18), n = j0 + k - 14. j0 multiple of 4 ->
    // pair starts even & 16B-aligned; a pair is fully valid or fully zero.
    float xr[WIN], xi[WIN];
#pragma unroll
    for (int kp = 0; kp < WIN / 2; kp++) {
        const int k = 2 * kp;
        const int n = j0 + k - 14;
        float4 v;
        if (n >= 0) v = *reinterpret_cast<const float4*>(xrow + n);
        else        v = make_float4(0.f, 0.f, 0.f, 0.f);
        xr[k]     = v.x; xi[k]     = v.y;
        xr[k + 1] = v.z; xi[k + 1] = v.w;
    }

    // Envelope a = |xc| (approx sqrt: ~2^-21 rel err, 0 -> 0), packed at both
    // parities: ae[h]=(a[2h],a[2h+1]) h=0..8; ao[h]=(a[2h+1],a[2h+2]) h=0..7.
    float a[WIN];
#pragma unroll
    for (int k = 0; k < WIN; k++)
        a[k] = sqrt_approx(fmaf(xr[k], xr[k], xi[k] * xi[k]));

    u64 ae[9], ao[8];
#pragma unroll
    for (int h = 0; h < 9; h++) ae[h] = pk2(a[2 * h], a[2 * h + 1]);
#pragma unroll
    for (int h = 0; h < 8; h++) ao[h] = pk2(a[2 * h + 1], a[2 * h + 2]);

    float or_[CH], oi_[CH];
#pragma unroll
    for (int c = 0; c < CH; c++) { or_[c] = 0.f; oi_[c] = 0.f; }

#pragma unroll
    for (int i = 0; i < Mm; i++) {
        const u64 w0p = sW0d[i];
        u64 F[CH / 2];

#pragma unroll
        for (int m = 0; m < Mm; m++) {
            const ulonglong2 w12 = *reinterpret_cast<const ulonglong2*>(&sWd[(i * Mm + m) * 4]);
            const u64 w3d = sWd[(i * Mm + m) * 4 + 2];
            const int s    = i + m;        // compile-time constant
            const int base = s >> 1;
#pragma unroll
            for (int cp = 0; cp < CH / 2; cp++) {
                // pair covers t_lo = 2*cp + s, t_hi = t_lo + 1 (t = c+i+m)
                const u64 av = (s & 1) ? ao[base + cp] : ae[base + cp];
                const u64 t1 = fma2(av, w3d, w12.y);
                const u64 t2 = fma2(av, t1,  w12.x);
                F[cp] = fma2(av, t2, (m == 0) ? w0p : F[cp]);
            }
        }

        // Tail: complex tap accumulation (scalar; xk parity varies with i).
#pragma unroll
        for (int cp = 0; cp < CH / 2; cp++) {
            float Flo, Fhi; upk2(F[cp], Flo, Fhi);
            const int c  = 2 * cp;
            const int xk = c + i + 7;      // x-index for n = j0+c+i-7
            or_[c]     = fmaf(xr[xk],     Flo, or_[c]);
            oi_[c]     = fmaf(xi[xk],     Flo, oi_[c]);
            or_[c + 1] = fmaf(xr[xk + 1], Fhi, or_[c + 1]);
            oi_[c + 1] = fmaf(xi[xk + 1], Fhi, oi_[c + 1]);
        }
    }

    // Vectorized store: 2x STG.128.
    float4* orow4 = reinterpret_cast<float4*>(out + (size_t)b * Tn + j0);
#pragma unroll
    for (int c4 = 0; c4 < CH / 2; c4++)
        orow4[c4] = make_float4(or_[2 * c4], oi_[2 * c4],
                                or_[2 * c4 + 1], oi_[2 * c4 + 1]);
}

extern "C" void kernel_launch(void* const* d_in, const int* in_sizes, int n_in,
                              void* d_out, int out_size)
{
    const float2* x = (const float2*)d_in[0];
    // d_in[1] = h_0 (unused)
    const float*  W = (const float*)d_in[2];
    float2* out = (float2*)d_out;

    const int total_threads = Bn * (Tn / CH);      // 262144
    const int grid = total_threads / TPB;          // 2048
    gmp_kernel<<<grid, TPB>>>(x, W, out);
}

// round 17
// speedup vs baseline: 1.1537x; 1.1366x over previous
#include <cuda_runtime.h>
#include <cstdint>

// GMP forward:
// out[b,j] = sum_{i=0..7} xc[b, j+i-7] * F_i(j+i-7)
// F_i(n)   = W[i,0] + sum_{m=0..7} a(n+m-7)*(w1 + a*(w2 + a*w3))   (Horner)
// with (w1,w2,w3) = W[i, 1+3m+{0,1,2}]; xc,a zero-extended for n<0.
// Two consecutive time samples per f32x2 lane pair (FFMA2).

constexpr int Bn  = 64;
constexpr int Tn  = 16384;
constexpr int Mm  = 8;
constexpr int CH  = 8;       // samples per thread
constexpr int TPB = 128;
constexpr int WIN = CH + 14; // 22

using u64 = unsigned long long;

union f2u { float2 f; u64 u; };

__device__ __forceinline__ u64 pk2(float lo, float hi) {
    f2u t; t.f = make_float2(lo, hi); return t.u;
}
__device__ __forceinline__ void upk2(u64 v, float& lo, float& hi) {
    f2u t; t.u = v; lo = t.f.x; hi = t.f.y;
}
__device__ __forceinline__ u64 fma2(u64 a, u64 b, u64 c) {
    u64 r;
    asm("fma.rn.f32x2 %0, %1, %2, %3;" : "=l"(r) : "l"(a), "l"(b), "l"(c));
    return r;
}
__device__ __forceinline__ float sqrt_approx(float x) {
    float r;
    asm("sqrt.approx.f32 %0, %1;" : "=f"(r) : "f"(x));
    return r;
}

__global__ __launch_bounds__(TPB, 5)
void gmp_kernel(const float2* __restrict__ x,     // (B,T) complex as float2
                const float*  __restrict__ W,     // (8,25)
                float2*       __restrict__ out)   // (B,T) complex as float2
{
    // Duplicated weight pairs: sWd[(i*8+m)*4 + d] = (w_{d+1}, w_{d+1});
    // stride 4 u64 = 32B keeps 16B alignment for the ulonglong2 load.
    __shared__ u64 sWd[Mm * Mm * 4];
    __shared__ u64 sW0d[Mm];
    for (int q = threadIdx.x; q < Mm * Mm; q += TPB) {
        const int i = q >> 3, m = q & 7;
        const float* wr = W + i * 25 + 1 + 3 * m;
        sWd[q * 4 + 0] = pk2(wr[0], wr[0]);
        sWd[q * 4 + 1] = pk2(wr[1], wr[1]);
        sWd[q * 4 + 2] = pk2(wr[2], wr[2]);
    }
    if (threadIdx.x < Mm) {
        const float w0 = W[threadIdx.x * 25];
        sW0d[threadIdx.x] = pk2(w0, w0);
    }
    __syncthreads();

    const int per_row = Tn / CH;                       // 2048
    const int idx = blockIdx.x * TPB + threadIdx.x;    // < B*per_row
    const int b   = idx >> 11;                         // idx / 2048
    const int j0  = (idx & (per_row - 1)) * CH;

    const float2* xrow = x + (size_t)b * Tn;

    // Complex window as native float2 pairs: k in [0,22), n = j0 + k - 14.
    // j0 is a multiple of 8 -> float4 loads are 16B-aligned; only j0 in {0,8}
    // (2 of 2048 threads per row) can touch n < 0.
    float2 xcw[WIN];
    if (j0 >= 14) {
#pragma unroll
        for (int kp = 0; kp < WIN / 2; kp++) {
            const float4 v = *reinterpret_cast<const float4*>(xrow + (j0 + 2 * kp - 14));
            xcw[2 * kp]     = make_float2(v.x, v.y);
            xcw[2 * kp + 1] = make_float2(v.z, v.w);
        }
    } else {
#pragma unroll
        for (int kp = 0; kp < WIN / 2; kp++) {
            const int n = j0 + 2 * kp - 14;
            float4 v;
            if (n >= 0) v = *reinterpret_cast<const float4*>(xrow + n);
            else        v = make_float4(0.f, 0.f, 0.f, 0.f);
            xcw[2 * kp]     = make_float2(v.x, v.y);
            xcw[2 * kp + 1] = make_float2(v.z, v.w);
        }
    }

    // Envelope a = |xc| (sqrt.approx: ~2^-21 rel err, 0 -> 0), placed into
    // dual-parity pair slots: ae[h]=(a[2h],a[2h+1]), ao[h]=(a[2h+1],a[2h+2]).
    float a[WIN];
#pragma unroll
    for (int k = 0; k < WIN; k++)
        a[k] = sqrt_approx(fmaf(xcw[k].x, xcw[k].x, xcw[k].y * xcw[k].y));

    f2u ae[11], ao[10];
#pragma unroll
    for (int h = 0; h < 11; h++) ae[h].f = make_float2(a[2 * h], a[2 * h + 1]);
#pragma unroll
    for (int h = 0; h < 10; h++) ao[h].f = make_float2(a[2 * h + 1], a[2 * h + 2]);

    float or_[CH], oi_[CH];
#pragma unroll
    for (int c = 0; c < CH; c++) { or_[c] = 0.f; oi_[c] = 0.f; }

#pragma unroll
    for (int i = 0; i < Mm; i++) {
        const u64 w0p = sW0d[i];
        u64 F[CH / 2];

#pragma unroll
        for (int m = 0; m < Mm; m++) {
            const ulonglong2 w12 = *reinterpret_cast<const ulonglong2*>(&sWd[(i * Mm + m) * 4]);
            const u64 w3d = sWd[(i * Mm + m) * 4 + 2];
            const int s    = i + m;        // compile-time constant
            const int base = s >> 1;
#pragma unroll
            for (int cp = 0; cp < CH / 2; cp++) {
                // pair covers t_lo = 2*cp + s, t_hi = t_lo + 1   (t = c+i+m)
                const u64 av = (s & 1) ? ao[base + cp].u : ae[base + cp].u;
                const u64 t1 = fma2(av, w3d, w12.y);
                const u64 t2 = fma2(av, t1,  w12.x);
                F[cp] = fma2(av, t2, (m == 0) ? w0p : F[cp]);
            }
        }

        // Tail: complex tap accumulation (scalar FFMA; pair halves are free).
#pragma unroll
        for (int cp = 0; cp < CH / 2; cp++) {
            float Flo, Fhi; upk2(F[cp], Flo, Fhi);
            const int c  = 2 * cp;
            const int xk = c + i + 7;      // x-index for n = j0+c+i-7
            or_[c]     = fmaf(xcw[xk].x,     Flo, or_[c]);
            oi_[c]     = fmaf(xcw[xk].y,     Flo, oi_[c]);
            or_[c + 1] = fmaf(xcw[xk + 1].x, Fhi, or_[c + 1]);
            oi_[c + 1] = fmaf(xcw[xk + 1].y, Fhi, oi_[c + 1]);
        }
    }

    // Vectorized store: 4x STG.128.
    float4* orow4 = reinterpret_cast<float4*>(out + (size_t)b * Tn + j0);
#pragma unroll
    for (int c4 = 0; c4 < CH / 2; c4++)
        orow4[c4] = make_float4(or_[2 * c4], oi_[2 * c4],
                                or_[2 * c4 + 1], oi_[2 * c4 + 1]);
}

extern "C" void kernel_launch(void* const* d_in, const int* in_sizes, int n_in,
                              void* d_out, int out_size)
{
    const float2* x = (const float2*)d_in[0];
    // d_in[1] = h_0 (unused)
    const float*  W = (const float*)d_in[2];
    float2* out = (float2*)d_out;

    const int total_threads = Bn * (Tn / CH);      // 131072
    const int grid = total_threads / TPB;          // 1024
    gmp_kernel<<<grid, TPB>>>(x, W, out);
}